// round 11
// baseline (speedup 1.0000x reference)
#include <cuda_runtime.h>
#include <math.h>
#include <stdint.h>

#define BATCH 2
#define SEQ   2048
#define DMODEL 1024
#define HEADS 16
#define HD    64
#define QKV_N (3*DMODEL)       // 3072
#define MROWS (BATCH*SEQ)      // 4096

__device__ float g_qkv[(size_t)MROWS * QKV_N];     // [B*S, 3072] (tf32-rounded)
__device__ float g_att[(size_t)MROWS * DMODEL];    // [B*S, 1024] (tf32-rounded)
__device__ float g_xr[(size_t)MROWS * DMODEL];     // rounded x
__device__ float g_wqkvr[(size_t)DMODEL * QKV_N];  // rounded w_qkv
__device__ float g_woutr[(size_t)DMODEL * DMODEL]; // rounded w_out

// ===========================================================================
// helpers
// ===========================================================================
__device__ __forceinline__ float f2tf32(float f) {
    uint32_t r;
    asm("cvt.rna.tf32.f32 %0, %1;" : "=r"(r) : "f"(f));
    return __uint_as_float(r);
}
__device__ __forceinline__ uint32_t smem_u32(const void* p) {
    uint32_t a;
    asm("{ .reg .u64 t; cvta.to.shared.u64 t, %1; cvt.u32.u64 %0, t; }" : "=r"(a) : "l"(p));
    return a;
}
__device__ __forceinline__ void mma_tf32(float c[4], const uint32_t a[4], const uint32_t b[2]) {
    asm volatile(
        "mma.sync.aligned.m16n8k8.row.col.f32.tf32.tf32.f32 "
        "{%0,%1,%2,%3}, {%4,%5,%6,%7}, {%8,%9}, {%0,%1,%2,%3};"
        : "+f"(c[0]), "+f"(c[1]), "+f"(c[2]), "+f"(c[3])
        : "r"(a[0]), "r"(a[1]), "r"(a[2]), "r"(a[3]), "r"(b[0]), "r"(b[1]));
}
__device__ __forceinline__ void cp_async16(uint32_t saddr, const void* gptr) {
    asm volatile("cp.async.ca.shared.global [%0], [%1], 16;" :: "r"(saddr), "l"(gptr));
}
__device__ __forceinline__ void cp_commit() {
    asm volatile("cp.async.commit_group;" ::: "memory");
}
__device__ __forceinline__ void cp_wait0() {
    asm volatile("cp.async.wait_group 0;" ::: "memory");
}
__device__ __forceinline__ void cp_wait2() {
    asm volatile("cp.async.wait_group 2;" ::: "memory");
}

// ===========================================================================
// elementwise tf32 rounding pass (streaming)
// ===========================================================================
__global__ __launch_bounds__(256)
void round_tf32_kernel(const float* __restrict__ src, float* __restrict__ dst, int n4)
{
    int i = blockIdx.x * blockDim.x + threadIdx.x;
    if (i < n4) {
        float4 v = ((const float4*)src)[i];
        v.x = f2tf32(v.x); v.y = f2tf32(v.y); v.z = f2tf32(v.z); v.w = f2tf32(v.w);
        ((float4*)dst)[i] = v;
    }
}

// ===========================================================================
// tf32 mma.sync GEMM + bias, 4-stage cp.async pipeline (unchanged from R10).
// ===========================================================================
#define AS_P 20
#define BS_P 136
#define AS_FLOATS (128 * AS_P)
#define BS_FLOATS (16 * BS_P)
#define ST_FLOATS (AS_FLOATS + BS_FLOATS)
#define NSTAGE 4
#define GEMM_SMEM (NSTAGE * ST_FLOATS * sizeof(float))   // 75776

template <bool RND>
__global__ __launch_bounds__(256, 2)
void gemm_mma_kernel(const float* __restrict__ A, const float* __restrict__ W,
                     const float* __restrict__ bias, float* __restrict__ C,
                     int N, int K)
{
    extern __shared__ float smf[];
    const uint32_t smb = smem_u32(smf);

    const int t    = threadIdx.x;
    const int lane = t & 31;
    const int wid  = t >> 5;
    const int wm   = (wid >> 2) * 64;
    const int wn   = (wid & 3) * 32;
    const int g    = lane >> 2;
    const int t4   = lane & 3;
    const int m0   = blockIdx.y * 128;
    const int n0   = blockIdx.x * 128;

    const int ar = t >> 1;
    const int as0 = (t & 1) * 2;
    const int br = t >> 4;
    const int bs0 = (t & 15) * 2;

    float acc[4][4][4];
#pragma unroll
    for (int mi = 0; mi < 4; mi++)
#pragma unroll
        for (int ni = 0; ni < 4; ni++)
#pragma unroll
            for (int r = 0; r < 4; r++) acc[mi][ni][r] = 0.f;

    const int nch = K / 16;

    auto load_chunk = [&](int c, int s) {
        const uint32_t stA = smb + (uint32_t)(s * ST_FLOATS) * 4u;
        const uint32_t stB = stA + (uint32_t)AS_FLOATS * 4u;
        const float* Ab = A + (size_t)(m0 + ar) * K + c * 16 + as0 * 4;
        cp_async16(stA + (uint32_t)(ar * AS_P + as0 * 4) * 4u, Ab);
        cp_async16(stA + (uint32_t)(ar * AS_P + (as0 + 1) * 4) * 4u, Ab + 4);
        const float* Wb = W + (size_t)(c * 16 + br) * N + n0 + bs0 * 4;
        cp_async16(stB + (uint32_t)(br * BS_P + bs0 * 4) * 4u, Wb);
        cp_async16(stB + (uint32_t)(br * BS_P + (bs0 + 1) * 4) * 4u, Wb + 4);
    };

#pragma unroll
    for (int c = 0; c < NSTAGE - 1; c++) { load_chunk(c, c); cp_commit(); }

    for (int c = 0; c < nch; c++) {
        cp_wait2();
        __syncthreads();

        if (c + NSTAGE - 1 < nch) load_chunk(c + NSTAGE - 1, (c + NSTAGE - 1) & (NSTAGE - 1));
        cp_commit();

        const int s = c & (NSTAGE - 1);
        const float* as_ = smf + s * ST_FLOATS;
        const float* bs_ = as_ + AS_FLOATS;

#pragma unroll
        for (int ks = 0; ks < 2; ks++) {
            const int kk = ks * 8;
            uint32_t af[4][4], bf[4][2];
#pragma unroll
            for (int mi = 0; mi < 4; mi++) {
                int r0 = wm + mi * 16 + g;
                af[mi][0] = __float_as_uint(as_[r0 * AS_P + kk + t4]);
                af[mi][1] = __float_as_uint(as_[(r0 + 8) * AS_P + kk + t4]);
                af[mi][2] = __float_as_uint(as_[r0 * AS_P + kk + t4 + 4]);
                af[mi][3] = __float_as_uint(as_[(r0 + 8) * AS_P + kk + t4 + 4]);
            }
#pragma unroll
            for (int ni = 0; ni < 4; ni++) {
                int cc = wn + ni * 8 + g;
                bf[ni][0] = __float_as_uint(bs_[(kk + t4) * BS_P + cc]);
                bf[ni][1] = __float_as_uint(bs_[(kk + t4 + 4) * BS_P + cc]);
            }
#pragma unroll
            for (int mi = 0; mi < 4; mi++)
#pragma unroll
                for (int ni = 0; ni < 4; ni++)
                    mma_tf32(acc[mi][ni], af[mi], bf[ni]);
        }
    }

#pragma unroll
    for (int mi = 0; mi < 4; mi++) {
        int row = m0 + wm + mi * 16 + g;
#pragma unroll
        for (int ni = 0; ni < 4; ni++) {
            int col = n0 + wn + ni * 8 + 2 * t4;
            float2 bv = *(const float2*)(bias + col);
            float2 v0, v1;
            if (RND) {
                v0 = make_float2(f2tf32(acc[mi][ni][0] + bv.x), f2tf32(acc[mi][ni][1] + bv.y));
                v1 = make_float2(f2tf32(acc[mi][ni][2] + bv.x), f2tf32(acc[mi][ni][3] + bv.y));
            } else {
                v0 = make_float2(acc[mi][ni][0] + bv.x, acc[mi][ni][1] + bv.y);
                v1 = make_float2(acc[mi][ni][2] + bv.x, acc[mi][ni][3] + bv.y);
            }
            *(float2*)(C + (size_t)row * N + col)       = v0;
            *(float2*)(C + (size_t)(row + 8) * N + col) = v1;
        }
    }
}

// ===========================================================================
// tf32 mma.sync flash attention:
//  - cp.async double-buffered K/V (K pitch 68, V raw [key][d] pitch 72)
//  - ONE __syncthreads per tile; fill of kt+1 overlaps compute of kt
//  - P stays in registers; PV A-fragments built by quad shfl (no Ps smem)
// qkv is pre-rounded tf32 -> no cvts.
// ===========================================================================
#define KP 68
#define VP 72
#define QS_F (128*68)               // 8704 floats
#define KV_KF (64*KP)               // 4352
#define KV_VF (64*VP)               // 4608
#define STG_F (KV_KF + KV_VF)       // 8960
#define ATT_SMEM ((QS_F + 2*STG_F) * sizeof(float))   // 106496 B

__global__ __launch_bounds__(256, 2)
void attn_mma_kernel(const float* __restrict__ qkv, const float* __restrict__ mask,
                     float* __restrict__ att)
{
    extern __shared__ float smf[];
    const uint32_t smb = smem_u32(smf);
    float* Qs = smf;

    const int t    = threadIdx.x;
    const int lane = t & 31;
    const int wid  = t >> 5;
    const int g    = lane >> 2;
    const int t4   = lane & 3;
    const int bh   = blockIdx.y;
    const int b    = bh / HEADS;
    const int h    = bh % HEADS;
    const int q0   = blockIdx.x * 128;

    const int qrow = wid * 16 + g;
    const float* qsw = Qs + qrow * 68;

    // shfl sources for PV A-fragment construction
    const int srcA = (lane & 28) | (t4 >> 1);   // 4g + t4/2
    const int srcB = srcA + 2;
    const bool oddc = (t4 & 1) != 0;

    // cp.async fill mapping: thread t -> row t>>2, 16-float col group (t&3)*16
    const int frow = t >> 2;
    const int fseg = (t & 3) * 16;
    const float* kvsrc = qkv + ((size_t)(b * SEQ)) * QKV_N + h * (3 * HD);

    auto load_tile = [&](int kt, int s) {
        const float* src = kvsrc + (size_t)(kt * 64 + frow) * QKV_N;
        const uint32_t kdst = smb + (uint32_t)(QS_F + s * STG_F + frow * KP + fseg) * 4u;
        const uint32_t vdst = smb + (uint32_t)(QS_F + s * STG_F + KV_KF + frow * VP + fseg) * 4u;
#pragma unroll
        for (int i = 0; i < 4; i++) {
            cp_async16(kdst + i * 16u, src + HD + fseg + i * 4);      // K
            cp_async16(vdst + i * 16u, src + 2 * HD + fseg + i * 4);  // V
        }
    };

    // ---- Q tile -> smem (scale 1/8 exact; values pre-rounded) ----
    {
        const float* qb = qkv + ((size_t)(b * SEQ + q0)) * QKV_N + h * (3 * HD);
#pragma unroll
        for (int i = 0; i < 8; i++) {
            int idx = t + i * 256;
            int row = idx >> 4, seg = idx & 15;
            float4 v = *(const float4*)(qb + (size_t)row * QKV_N + seg * 4);
            float* d = Qs + row * 68 + seg * 4;
            d[0] = v.x * 0.125f; d[1] = v.y * 0.125f;
            d[2] = v.z * 0.125f; d[3] = v.w * 0.125f;
        }
    }

    float m0 = -1e30f, m1 = -1e30f, l0 = 0.f, l1 = 0.f;
    float acc[8][4];
#pragma unroll
    for (int ni = 0; ni < 8; ni++)
#pragma unroll
        for (int r = 0; r < 4; r++) acc[ni][r] = 0.f;

    load_tile(0, 0);
    cp_commit();

    const int NT = SEQ / 64;
    for (int kt = 0; kt < NT; kt++) {
        const int s = kt & 1;
        cp_wait0();
        __syncthreads();   // stage s filled; everyone past last epoch's reads of s^1

        if (kt + 1 < NT) { load_tile(kt + 1, s ^ 1); cp_commit(); }

        const float* Ks = smf + QS_F + s * STG_F;
        const float* Vs = Ks + KV_KF;

        // ---- scores = Q @ K^T ----
        float sc[8][4];
#pragma unroll
        for (int ni = 0; ni < 8; ni++)
#pragma unroll
            for (int r = 0; r < 4; r++) sc[ni][r] = 0.f;

#pragma unroll
        for (int kk = 0; kk < 64; kk += 8) {
            uint32_t af[4];
            af[0] = __float_as_uint(qsw[kk + t4]);
            af[1] = __float_as_uint(qsw[8 * 68 + kk + t4]);
            af[2] = __float_as_uint(qsw[kk + t4 + 4]);
            af[3] = __float_as_uint(qsw[8 * 68 + kk + t4 + 4]);
#pragma unroll
            for (int ni = 0; ni < 8; ni++) {
                uint32_t bf[2];
                bf[0] = __float_as_uint(Ks[(ni * 8 + g) * KP + kk + t4]);
                bf[1] = __float_as_uint(Ks[(ni * 8 + g) * KP + kk + t4 + 4]);
                mma_tf32(sc[ni], af, bf);
            }
        }

        // ---- + mask, online softmax; sc <- rounded exp (P in registers) ----
        {
            const int k0 = kt * 64;
            const float* mr0 = mask + (size_t)(q0 + qrow) * SEQ + k0 + 2 * t4;
            const float* mr1 = mr0 + 8 * SEQ;
            float mx0 = -1e30f, mx1 = -1e30f;
#pragma unroll
            for (int ni = 0; ni < 8; ni++) {
                float2 a = *(const float2*)(mr0 + 8 * ni);
                float2 c = *(const float2*)(mr1 + 8 * ni);
                sc[ni][0] += a.x; sc[ni][1] += a.y;
                sc[ni][2] += c.x; sc[ni][3] += c.y;
                mx0 = fmaxf(mx0, fmaxf(sc[ni][0], sc[ni][1]));
                mx1 = fmaxf(mx1, fmaxf(sc[ni][2], sc[ni][3]));
            }
#pragma unroll
            for (int off = 1; off <= 2; off <<= 1) {
                mx0 = fmaxf(mx0, __shfl_xor_sync(0xffffffffu, mx0, off));
                mx1 = fmaxf(mx1, __shfl_xor_sync(0xffffffffu, mx1, off));
            }
            float mn0 = fmaxf(m0, mx0), mn1 = fmaxf(m1, mx1);
            float c0 = __expf(m0 - mn0), c1 = __expf(m1 - mn1);
            float rs0 = 0.f, rs1 = 0.f;
#pragma unroll
            for (int ni = 0; ni < 8; ni++) {
                sc[ni][0] = f2tf32(__expf(sc[ni][0] - mn0));
                sc[ni][1] = f2tf32(__expf(sc[ni][1] - mn0));
                sc[ni][2] = f2tf32(__expf(sc[ni][2] - mn1));
                sc[ni][3] = f2tf32(__expf(sc[ni][3] - mn1));
                rs0 += sc[ni][0] + sc[ni][1];
                rs1 += sc[ni][2] + sc[ni][3];
            }
#pragma unroll
            for (int off = 1; off <= 2; off <<= 1) {
                rs0 += __shfl_xor_sync(0xffffffffu, rs0, off);
                rs1 += __shfl_xor_sync(0xffffffffu, rs1, off);
            }
            l0 = l0 * c0 + rs0; l1 = l1 * c1 + rs1;
            m0 = mn0; m1 = mn1;
#pragma unroll
            for (int ni = 0; ni < 8; ni++) {
                acc[ni][0] *= c0; acc[ni][1] *= c0;
                acc[ni][2] *= c1; acc[ni][3] *= c1;
            }
        }

        // ---- acc += P @ V : A-frags via quad shfl from sc; B from raw V ----
#pragma unroll
        for (int kk8 = 0; kk8 < 8; kk8++) {
            const int kk = kk8 * 8;
            float p00 = __shfl_sync(0xffffffffu, sc[kk8][0], srcA);
            float p01 = __shfl_sync(0xffffffffu, sc[kk8][1], srcA);
            float p10 = __shfl_sync(0xffffffffu, sc[kk8][2], srcA);
            float p11 = __shfl_sync(0xffffffffu, sc[kk8][3], srcA);
            float q00 = __shfl_sync(0xffffffffu, sc[kk8][0], srcB);
            float q01 = __shfl_sync(0xffffffffu, sc[kk8][1], srcB);
            float q10 = __shfl_sync(0xffffffffu, sc[kk8][2], srcB);
            float q11 = __shfl_sync(0xffffffffu, sc[kk8][3], srcB);
            uint32_t af[4];
            af[0] = __float_as_uint(oddc ? p01 : p00);   // P[r0][kk+t4]
            af[1] = __float_as_uint(oddc ? p11 : p10);   // P[r1][kk+t4]
            af[2] = __float_as_uint(oddc ? q01 : q00);   // P[r0][kk+t4+4]
            af[3] = __float_as_uint(oddc ? q11 : q10);   // P[r1][kk+t4+4]
#pragma unroll
            for (int ni = 0; ni < 8; ni++) {
                uint32_t bf[2];
                bf[0] = __float_as_uint(Vs[(kk + t4) * VP + ni * 8 + g]);
                bf[1] = __float_as_uint(Vs[(kk + t4 + 4) * VP + ni * 8 + g]);
                mma_tf32(acc[ni], af, bf);
            }
        }
    }

    // ---- normalize + store, tf32-rounded (out-proj consumes as tf32) ----
    {
        float inv0 = 1.f / l0, inv1 = 1.f / l1;
        float* o0 = att + (size_t)(b * SEQ + q0 + qrow) * DMODEL + h * HD + 2 * t4;
        float* o1 = o0 + 8 * DMODEL;
#pragma unroll
        for (int ni = 0; ni < 8; ni++) {
            *(float2*)(o0 + 8 * ni) = make_float2(f2tf32(acc[ni][0] * inv0),
                                                  f2tf32(acc[ni][1] * inv0));
            *(float2*)(o1 + 8 * ni) = make_float2(f2tf32(acc[ni][2] * inv1),
                                                  f2tf32(acc[ni][3] * inv1));
        }
    }
}

// ---------------------------------------------------------------------------
extern "C" void kernel_launch(void* const* d_in, const int* in_sizes, int n_in,
                              void* d_out, int out_size)
{
    const float* x     = (const float*)d_in[0];
    const float* mask  = (const float*)d_in[1];
    const float* w_qkv = (const float*)d_in[2];
    const float* b_qkv = (const float*)d_in[3];
    const float* w_out = (const float*)d_in[4];
    const float* b_out = (const float*)d_in[5];
    float* out = (float*)d_out;

    float* qkv;   cudaGetSymbolAddress((void**)&qkv,   g_qkv);
    float* att;   cudaGetSymbolAddress((void**)&att,   g_att);
    float* xr;    cudaGetSymbolAddress((void**)&xr,    g_xr);
    float* wqkvr; cudaGetSymbolAddress((void**)&wqkvr, g_wqkvr);
    float* woutr; cudaGetSymbolAddress((void**)&woutr, g_woutr);

    cudaFuncSetAttribute(gemm_mma_kernel<true>, cudaFuncAttributeMaxDynamicSharedMemorySize,
                         (int)GEMM_SMEM);
    cudaFuncSetAttribute(gemm_mma_kernel<false>, cudaFuncAttributeMaxDynamicSharedMemorySize,
                         (int)GEMM_SMEM);
    cudaFuncSetAttribute(attn_mma_kernel, cudaFuncAttributeMaxDynamicSharedMemorySize,
                         (int)ATT_SMEM);

    // 0) pre-round operands to tf32
    round_tf32_kernel<<<(MROWS * DMODEL / 4 + 255) / 256, 256>>>(x, xr, MROWS * DMODEL / 4);
    round_tf32_kernel<<<(DMODEL * QKV_N / 4 + 255) / 256, 256>>>(w_qkv, wqkvr, DMODEL * QKV_N / 4);
    round_tf32_kernel<<<(DMODEL * DMODEL / 4 + 255) / 256, 256>>>(w_out, woutr, DMODEL * DMODEL / 4);

    // 1) QKV projection
    {
        dim3 grid(QKV_N / 128, MROWS / 128);
        gemm_mma_kernel<true><<<grid, 256, GEMM_SMEM>>>(xr, wqkvr, b_qkv, qkv, QKV_N, DMODEL);
    }
    // 2) attention (single-barrier pipelined, P-in-regs)
    {
        dim3 grid(SEQ / 128, BATCH * HEADS);
        attn_mma_kernel<<<grid, 256, ATT_SMEM>>>(qkv, mask, att);
    }
    // 3) output projection
    {
        dim3 grid(DMODEL / 128, MROWS / 128);
        gemm_mma_kernel<false><<<grid, 256, GEMM_SMEM>>>(att, woutr, b_out, out, DMODEL, DMODEL);
    }
}

// round 12
// speedup vs baseline: 1.7299x; 1.7299x over previous
#include <cuda_runtime.h>
#include <cuda_fp16.h>
#include <math.h>
#include <stdint.h>

#define BATCH 2
#define SEQ   2048
#define DMODEL 1024
#define HEADS 16
#define HD    64
#define QKV_N (3*DMODEL)       // 3072
#define MROWS (BATCH*SEQ)      // 4096

__device__ __half g_xh[(size_t)MROWS * DMODEL];     // x as half [M][1024]
__device__ __half g_wqkvh[(size_t)QKV_N * DMODEL];  // w_qkv^T as half [3072][1024]
__device__ __half g_wouth[(size_t)DMODEL * DMODEL]; // w_out^T as half [1024][1024]
__device__ __half g_qkvh[(size_t)MROWS * QKV_N];    // qkv as half [M][3072]
__device__ __half g_vth[(size_t)BATCH * HEADS * HD * SEQ]; // V^T [bh][d][key]
__device__ __half g_atth[(size_t)MROWS * DMODEL];   // attention out half [M][1024]

// ===========================================================================
// helpers
// ===========================================================================
__device__ __forceinline__ uint32_t smem_u32(const void* p) {
    uint32_t a;
    asm("{ .reg .u64 t; cvta.to.shared.u64 t, %1; cvt.u32.u64 %0, t; }" : "=r"(a) : "l"(p));
    return a;
}
__device__ __forceinline__ void mma_f16(float c[4], const uint32_t a[4], const uint32_t b[2]) {
    asm volatile(
        "mma.sync.aligned.m16n8k16.row.col.f32.f16.f16.f32 "
        "{%0,%1,%2,%3}, {%4,%5,%6,%7}, {%8,%9}, {%0,%1,%2,%3};"
        : "+f"(c[0]), "+f"(c[1]), "+f"(c[2]), "+f"(c[3])
        : "r"(a[0]), "r"(a[1]), "r"(a[2]), "r"(a[3]), "r"(b[0]), "r"(b[1]));
}
__device__ __forceinline__ void cp_async16(uint32_t saddr, const void* gptr) {
    asm volatile("cp.async.ca.shared.global [%0], [%1], 16;" :: "r"(saddr), "l"(gptr));
}
__device__ __forceinline__ void cp_commit() {
    asm volatile("cp.async.commit_group;" ::: "memory");
}
__device__ __forceinline__ void cp_wait0() {
    asm volatile("cp.async.wait_group 0;" ::: "memory");
}
__device__ __forceinline__ void cp_wait2() {
    asm volatile("cp.async.wait_group 2;" ::: "memory");
}
__device__ __forceinline__ uint32_t pack_h2(float lo, float hi) {
    __half2 h = __floats2half2_rn(lo, hi);
    return *reinterpret_cast<uint32_t*>(&h);
}

// ===========================================================================
// conversion kernels
// ===========================================================================
__global__ __launch_bounds__(256)
void cvt_half_kernel(const float* __restrict__ src, __half* __restrict__ dst, int n2)
{
    int i = blockIdx.x * blockDim.x + threadIdx.x;
    if (i < n2) {
        float2 v = ((const float2*)src)[i];
        ((__half2*)dst)[i] = __floats2half2_rn(v.x, v.y);
    }
}

// W[K][N] fp32 -> Wh[N][K] half
__global__ __launch_bounds__(256)
void transpose_cvt_kernel(const float* __restrict__ W, __half* __restrict__ Wh, int K, int N)
{
    __shared__ float tile[32][33];
    int bx = blockIdx.x * 32;   // n
    int by = blockIdx.y * 32;   // k
    int tx = threadIdx.x & 31, ty = threadIdx.x >> 5;
#pragma unroll
    for (int i = 0; i < 32; i += 8)
        tile[ty + i][tx] = W[(size_t)(by + ty + i) * N + bx + tx];
    __syncthreads();
#pragma unroll
    for (int i = 0; i < 32; i += 8)
        Wh[(size_t)(bx + ty + i) * K + by + tx] = __float2half_rn(tile[tx][ty + i]);
}

// per (bh): V [2048 keys][64 d] (inside qkvh) -> vth [64 d][2048 keys]
__global__ __launch_bounds__(256)
void vtrans_kernel(const __half* __restrict__ qkvh, __half* __restrict__ vth)
{
    __shared__ __half tile[64 * 72];
    const int kt = blockIdx.x;          // key tile (64)
    const int bh = blockIdx.y;
    const int b  = bh / HEADS, h = bh % HEADS;
    const int t  = threadIdx.x;

    // read 64 keys x 64 d (coalesced 16B chunks)
#pragma unroll
    for (int i = 0; i < 2; i++) {
        int idx = t + i * 256;
        int key = idx >> 3, part = idx & 7;   // 8 x uint4 per key row
        const uint4* src = (const uint4*)(qkvh + (size_t)(b * SEQ + kt * 64 + key) * QKV_N
                                          + h * (3 * HD) + 2 * HD + part * 8);
        *(uint4*)(tile + key * 72 + part * 8) = *src;
    }
    __syncthreads();

    // write 64 d rows x 64 keys
    const int d = t >> 2, ks = (t & 3) * 16;
    __half tmp[16];
#pragma unroll
    for (int k = 0; k < 16; k++) tmp[k] = tile[(ks + k) * 72 + d];
    __half* dst = vth + ((size_t)bh * HD + d) * SEQ + kt * 64 + ks;
    *(uint4*)dst       = *(uint4*)tmp;
    *(uint4*)(dst + 8) = *(uint4*)(tmp + 8);
}

// ===========================================================================
// fp16 mma GEMM + bias:  C[M,N] = A[M,K]h @ Bt[N,K]h^T + bias
// 128x128 CTA, BK=32 (2 ksteps of m16n8k16), 4-stage cp.async, 8 warps 64x32.
// smem pitch 40 halves (80B): fragment banks g*20+t4 mod 32 all distinct.
// ===========================================================================
#define GP 40
#define G_ST (128 * GP)                 // halves per operand stage
#define G_STAGE (2 * G_ST)              // A + B
#define GNS 4
#define GEMM_SMEM (GNS * G_STAGE * sizeof(__half))   // 81920

template <bool OUTHALF>
__global__ __launch_bounds__(256, 2)
void gemm_h_kernel(const __half* __restrict__ A, const __half* __restrict__ Bt,
                   const float* __restrict__ bias, void* __restrict__ Cp,
                   int N, int K)
{
    extern __shared__ __half smh[];
    const uint32_t smb = smem_u32(smh);

    const int t    = threadIdx.x;
    const int lane = t & 31;
    const int wid  = t >> 5;
    const int wm   = (wid >> 2) * 64;
    const int wn   = (wid & 3) * 32;
    const int g    = lane >> 2;
    const int t4   = lane & 3;
    const int m0   = blockIdx.y * 128;
    const int n0   = blockIdx.x * 128;

    const int frow = t >> 1;            // 128 rows, 2 threads each
    const int fseg = (t & 1) * 16;      // halves offset (32B per thread, 2x16B)

    float acc[4][4][4];
#pragma unroll
    for (int mi = 0; mi < 4; mi++)
#pragma unroll
        for (int ni = 0; ni < 4; ni++)
#pragma unroll
            for (int r = 0; r < 4; r++) acc[mi][ni][r] = 0.f;

    const int nch = K / 32;

    auto load_chunk = [&](int c, int s) {
        const uint32_t stA = smb + (uint32_t)(s * G_STAGE) * 2u;
        const uint32_t stB = stA + (uint32_t)G_ST * 2u;
        const __half* Ab = A + (size_t)(m0 + frow) * K + c * 32 + fseg;
        cp_async16(stA + (uint32_t)(frow * GP + fseg) * 2u, Ab);
        cp_async16(stA + (uint32_t)(frow * GP + fseg + 8) * 2u, Ab + 8);
        const __half* Bb = Bt + (size_t)(n0 + frow) * K + c * 32 + fseg;
        cp_async16(stB + (uint32_t)(frow * GP + fseg) * 2u, Bb);
        cp_async16(stB + (uint32_t)(frow * GP + fseg + 8) * 2u, Bb + 8);
    };

#pragma unroll
    for (int c = 0; c < GNS - 1; c++) { load_chunk(c, c); cp_commit(); }

    for (int c = 0; c < nch; c++) {
        cp_wait2();
        __syncthreads();

        if (c + GNS - 1 < nch) load_chunk(c + GNS - 1, (c + GNS - 1) & (GNS - 1));
        cp_commit();

        const int s = c & (GNS - 1);
        const __half* as_ = smh + s * G_STAGE;
        const __half* bs_ = as_ + G_ST;

#pragma unroll
        for (int ks = 0; ks < 2; ks++) {
            const int kk = ks * 16;
            uint32_t af[4][4], bf[4][2];
#pragma unroll
            for (int mi = 0; mi < 4; mi++) {
                int r0 = wm + mi * 16 + g;
                af[mi][0] = *(const uint32_t*)(as_ + r0 * GP + kk + 2 * t4);
                af[mi][1] = *(const uint32_t*)(as_ + (r0 + 8) * GP + kk + 2 * t4);
                af[mi][2] = *(const uint32_t*)(as_ + r0 * GP + kk + 2 * t4 + 8);
                af[mi][3] = *(const uint32_t*)(as_ + (r0 + 8) * GP + kk + 2 * t4 + 8);
            }
#pragma unroll
            for (int ni = 0; ni < 4; ni++) {
                int cc = wn + ni * 8 + g;
                bf[ni][0] = *(const uint32_t*)(bs_ + cc * GP + kk + 2 * t4);
                bf[ni][1] = *(const uint32_t*)(bs_ + cc * GP + kk + 2 * t4 + 8);
            }
#pragma unroll
            for (int mi = 0; mi < 4; mi++)
#pragma unroll
                for (int ni = 0; ni < 4; ni++)
                    mma_f16(acc[mi][ni], af[mi], bf[ni]);
        }
    }

#pragma unroll
    for (int mi = 0; mi < 4; mi++) {
        int row = m0 + wm + mi * 16 + g;
#pragma unroll
        for (int ni = 0; ni < 4; ni++) {
            int col = n0 + wn + ni * 8 + 2 * t4;
            float2 bv = *(const float2*)(bias + col);
            if (OUTHALF) {
                __half* C = (__half*)Cp;
                *(uint32_t*)(C + (size_t)row * N + col) =
                    pack_h2(acc[mi][ni][0] + bv.x, acc[mi][ni][1] + bv.y);
                *(uint32_t*)(C + (size_t)(row + 8) * N + col) =
                    pack_h2(acc[mi][ni][2] + bv.x, acc[mi][ni][3] + bv.y);
            } else {
                float* C = (float*)Cp;
                *(float2*)(C + (size_t)row * N + col) =
                    make_float2(acc[mi][ni][0] + bv.x, acc[mi][ni][1] + bv.y);
                *(float2*)(C + (size_t)(row + 8) * N + col) =
                    make_float2(acc[mi][ni][2] + bv.x, acc[mi][ni][3] + bv.y);
            }
        }
    }
}

// ===========================================================================
// fp16 mma flash attention.
// 8 warps, 128 queries/CTA, 64-key tiles; warp owns 16 full score rows.
// Q/K [row][d] half pitch 72 (banks g*36+t4 mod 32 distinct); V^T [d][key].
// PV A-fragments come straight from QK accumulators (layout-compatible).
// ===========================================================================
#define AP 72
#define Q_F (128 * AP)                  // halves
#define KV_F (64 * AP)                  // halves per K (or V) tile
#define A_STG (2 * KV_F)                // K + V per stage
#define ATT_SMEM ((Q_F + 2 * A_STG) * sizeof(__half))   // 55296 B

__global__ __launch_bounds__(256, 2)
void attn_h_kernel(const __half* __restrict__ qkvh, const __half* __restrict__ vth,
                   const float* __restrict__ mask, __half* __restrict__ att)
{
    extern __shared__ __half smh[];
    const uint32_t smb = smem_u32(smh);
    __half* Qs = smh;

    const int t    = threadIdx.x;
    const int lane = t & 31;
    const int wid  = t >> 5;
    const int g    = lane >> 2;
    const int t4   = lane & 3;
    const int bh   = blockIdx.y;
    const int b    = bh / HEADS;
    const int h    = bh % HEADS;
    const int q0   = blockIdx.x * 128;

    const int qrow = wid * 16 + g;
    const __half* qsw = Qs + qrow * AP;

    // K/V fill mapping: thread t -> row t>>2, 32B chunk (t&3)
    const int frow = t >> 2;
    const int fseg = (t & 3) * 16;      // halves

    auto load_tile = [&](int kt, int s) {
        const __half* ksrc = qkvh + (size_t)(b * SEQ + kt * 64 + frow) * QKV_N
                           + h * (3 * HD) + HD + fseg;
        const __half* vsrc = vth + ((size_t)bh * HD + frow) * SEQ + kt * 64 + fseg;
        const uint32_t kdst = smb + (uint32_t)(Q_F + s * A_STG + frow * AP + fseg) * 2u;
        const uint32_t vdst = smb + (uint32_t)(Q_F + s * A_STG + KV_F + frow * AP + fseg) * 2u;
        cp_async16(kdst, ksrc);
        cp_async16(kdst + 16u, ksrc + 8);
        cp_async16(vdst, vsrc);
        cp_async16(vdst + 16u, vsrc + 8);
    };

    // ---- Q tile -> smem with exact x0.125 (hmul2 by power of 2) ----
    {
        const __half2 sc8 = __floats2half2_rn(0.125f, 0.125f);
#pragma unroll
        for (int i = 0; i < 4; i++) {
            int idx = t + i * 256;
            int row = idx >> 3, part = idx & 7;
            const uint4* src = (const uint4*)(qkvh + (size_t)(b * SEQ + q0 + row) * QKV_N
                                              + h * (3 * HD) + part * 8);
            uint4 v = *src;
            __half2* hv = (__half2*)&v;
            hv[0] = __hmul2(hv[0], sc8); hv[1] = __hmul2(hv[1], sc8);
            hv[2] = __hmul2(hv[2], sc8); hv[3] = __hmul2(hv[3], sc8);
            *(uint4*)(Qs + row * AP + part * 8) = v;
        }
    }

    float m0 = -1e30f, m1 = -1e30f, l0 = 0.f, l1 = 0.f;
    float acc[8][4];
#pragma unroll
    for (int ni = 0; ni < 8; ni++)
#pragma unroll
        for (int r = 0; r < 4; r++) acc[ni][r] = 0.f;

    load_tile(0, 0);
    cp_commit();

    const int NT = SEQ / 64;
    for (int kt = 0; kt < NT; kt++) {
        const int s = kt & 1;
        cp_wait0();
        __syncthreads();

        if (kt + 1 < NT) { load_tile(kt + 1, s ^ 1); cp_commit(); }

        const __half* Ks = smh + Q_F + s * A_STG;
        const __half* Vs = Ks + KV_F;

        // ---- scores = Q @ K^T  (4 ksteps of K=16) ----
        float sc[8][4];
#pragma unroll
        for (int ni = 0; ni < 8; ni++)
#pragma unroll
            for (int r = 0; r < 4; r++) sc[ni][r] = 0.f;

#pragma unroll
        for (int kk = 0; kk < 64; kk += 16) {
            uint32_t af[4];
            af[0] = *(const uint32_t*)(qsw + kk + 2 * t4);
            af[1] = *(const uint32_t*)(qsw + 8 * AP + kk + 2 * t4);
            af[2] = *(const uint32_t*)(qsw + kk + 2 * t4 + 8);
            af[3] = *(const uint32_t*)(qsw + 8 * AP + kk + 2 * t4 + 8);
#pragma unroll
            for (int ni = 0; ni < 8; ni++) {
                uint32_t bf[2];
                bf[0] = *(const uint32_t*)(Ks + (ni * 8 + g) * AP + kk + 2 * t4);
                bf[1] = *(const uint32_t*)(Ks + (ni * 8 + g) * AP + kk + 2 * t4 + 8);
                mma_f16(sc[ni], af, bf);
            }
        }

        // ---- + mask, online softmax; sc <- half-rounded exp ----
        {
            const int k0 = kt * 64;
            const float* mr0 = mask + (size_t)(q0 + qrow) * SEQ + k0 + 2 * t4;
            const float* mr1 = mr0 + 8 * SEQ;
            float mx0 = -1e30f, mx1 = -1e30f;
#pragma unroll
            for (int ni = 0; ni < 8; ni++) {
                float2 a = *(const float2*)(mr0 + 8 * ni);
                float2 c = *(const float2*)(mr1 + 8 * ni);
                sc[ni][0] += a.x; sc[ni][1] += a.y;
                sc[ni][2] += c.x; sc[ni][3] += c.y;
                mx0 = fmaxf(mx0, fmaxf(sc[ni][0], sc[ni][1]));
                mx1 = fmaxf(mx1, fmaxf(sc[ni][2], sc[ni][3]));
            }
#pragma unroll
            for (int off = 1; off <= 2; off <<= 1) {
                mx0 = fmaxf(mx0, __shfl_xor_sync(0xffffffffu, mx0, off));
                mx1 = fmaxf(mx1, __shfl_xor_sync(0xffffffffu, mx1, off));
            }
            float mn0 = fmaxf(m0, mx0), mn1 = fmaxf(m1, mx1);
            float c0 = __expf(m0 - mn0), c1 = __expf(m1 - mn1);
            float rs0 = 0.f, rs1 = 0.f;
#pragma unroll
            for (int ni = 0; ni < 8; ni++) {
                sc[ni][0] = __half2float(__float2half_rn(__expf(sc[ni][0] - mn0)));
                sc[ni][1] = __half2float(__float2half_rn(__expf(sc[ni][1] - mn0)));
                sc[ni][2] = __half2float(__float2half_rn(__expf(sc[ni][2] - mn1)));
                sc[ni][3] = __half2float(__float2half_rn(__expf(sc[ni][3] - mn1)));
                rs0 += sc[ni][0] + sc[ni][1];
                rs1 += sc[ni][2] + sc[ni][3];
            }
#pragma unroll
            for (int off = 1; off <= 2; off <<= 1) {
                rs0 += __shfl_xor_sync(0xffffffffu, rs0, off);
                rs1 += __shfl_xor_sync(0xffffffffu, rs1, off);
            }
            l0 = l0 * c0 + rs0; l1 = l1 * c1 + rs1;
            m0 = mn0; m1 = mn1;
#pragma unroll
            for (int ni = 0; ni < 8; ni++) {
                acc[ni][0] *= c0; acc[ni][1] *= c0;
                acc[ni][2] *= c1; acc[ni][3] *= c1;
            }
        }

        // ---- acc += P @ V : A direct from accumulators, B from V^T ----
#pragma unroll
        for (int j = 0; j < 4; j++) {
            const int kk = j * 16;
            uint32_t af[4];
            af[0] = pack_h2(sc[2 * j][0],     sc[2 * j][1]);
            af[1] = pack_h2(sc[2 * j][2],     sc[2 * j][3]);
            af[2] = pack_h2(sc[2 * j + 1][0], sc[2 * j + 1][1]);
            af[3] = pack_h2(sc[2 * j + 1][2], sc[2 * j + 1][3]);
#pragma unroll
            for (int ni = 0; ni < 8; ni++) {
                uint32_t bf[2];
                bf[0] = *(const uint32_t*)(Vs + (ni * 8 + g) * AP + kk + 2 * t4);
                bf[1] = *(const uint32_t*)(Vs + (ni * 8 + g) * AP + kk + 2 * t4 + 8);
                mma_f16(acc[ni], af, bf);
            }
        }
    }

    // ---- normalize + store half ----
    {
        float inv0 = 1.f / l0, inv1 = 1.f / l1;
        __half* o0 = att + (size_t)(b * SEQ + q0 + qrow) * DMODEL + h * HD + 2 * t4;
        __half* o1 = o0 + 8 * DMODEL;
#pragma unroll
        for (int ni = 0; ni < 8; ni++) {
            *(uint32_t*)(o0 + 8 * ni) = pack_h2(acc[ni][0] * inv0, acc[ni][1] * inv0);
            *(uint32_t*)(o1 + 8 * ni) = pack_h2(acc[ni][2] * inv1, acc[ni][3] * inv1);
        }
    }
}

// ---------------------------------------------------------------------------
extern "C" void kernel_launch(void* const* d_in, const int* in_sizes, int n_in,
                              void* d_out, int out_size)
{
    const float* x     = (const float*)d_in[0];
    const float* mask  = (const float*)d_in[1];
    const float* w_qkv = (const float*)d_in[2];
    const float* b_qkv = (const float*)d_in[3];
    const float* w_out = (const float*)d_in[4];
    const float* b_out = (const float*)d_in[5];
    float* out = (float*)d_out;

    __half *xh, *wqkvh, *wouth, *qkvh, *vthp, *atth;
    cudaGetSymbolAddress((void**)&xh,    g_xh);
    cudaGetSymbolAddress((void**)&wqkvh, g_wqkvh);
    cudaGetSymbolAddress((void**)&wouth, g_wouth);
    cudaGetSymbolAddress((void**)&qkvh,  g_qkvh);
    cudaGetSymbolAddress((void**)&vthp,  g_vth);
    cudaGetSymbolAddress((void**)&atth,  g_atth);

    cudaFuncSetAttribute(gemm_h_kernel<true>, cudaFuncAttributeMaxDynamicSharedMemorySize,
                         (int)GEMM_SMEM);
    cudaFuncSetAttribute(gemm_h_kernel<false>, cudaFuncAttributeMaxDynamicSharedMemorySize,
                         (int)GEMM_SMEM);
    cudaFuncSetAttribute(attn_h_kernel, cudaFuncAttributeMaxDynamicSharedMemorySize,
                         (int)ATT_SMEM);

    // 0) convert operands to half (x row-major; weights transposed to [N][K])
    cvt_half_kernel<<<(MROWS * DMODEL / 2 + 255) / 256, 256>>>(x, xh, MROWS * DMODEL / 2);
    {
        dim3 g1(QKV_N / 32, DMODEL / 32);
        transpose_cvt_kernel<<<g1, 256>>>(w_qkv, wqkvh, DMODEL, QKV_N);
        dim3 g2(DMODEL / 32, DMODEL / 32);
        transpose_cvt_kernel<<<g2, 256>>>(w_out, wouth, DMODEL, DMODEL);
    }

    // 1) QKV projection (fp16 mma, half output)
    {
        dim3 grid(QKV_N / 128, MROWS / 128);
        gemm_h_kernel<true><<<grid, 256, GEMM_SMEM>>>(xh, wqkvh, b_qkv, qkvh, QKV_N, DMODEL);
    }

    // 1b) transpose V per (b,h): [key][d] -> [d][key]
    {
        dim3 grid(SEQ / 64, BATCH * HEADS);
        vtrans_kernel<<<grid, 256>>>(qkvh, vthp);
    }

    // 2) attention (fp16 mma flash)
    {
        dim3 grid(SEQ / 128, BATCH * HEADS);
        attn_h_kernel<<<grid, 256, ATT_SMEM>>>(qkvh, vthp, mask, atth);
    }

    // 3) output projection (fp16 mma, fp32 output)
    {
        dim3 grid(DMODEL / 128, MROWS / 128);
        gemm_h_kernel<false><<<grid, 256, GEMM_SMEM>>>(atth, wouth, b_out, out, DMODEL, DMODEL);
    }
}

// round 13
// speedup vs baseline: 1.7637x; 1.0195x over previous
#include <cuda_runtime.h>
#include <cuda_fp16.h>
#include <math.h>
#include <stdint.h>

#define BATCH 2
#define SEQ   2048
#define DMODEL 1024
#define HEADS 16
#define HD    64
#define QKV_N (3*DMODEL)       // 3072
#define MROWS (BATCH*SEQ)      // 4096

__device__ __half g_xh[(size_t)MROWS * DMODEL];     // x as half [M][1024]
__device__ __half g_wqkvh[(size_t)QKV_N * DMODEL];  // w_qkv^T as half [3072][1024]
__device__ __half g_wouth[(size_t)DMODEL * DMODEL]; // w_out^T as half [1024][1024]
__device__ __half g_qkvh[(size_t)MROWS * QKV_N];    // qkv as half [M][3072]
__device__ __half g_vth[(size_t)BATCH * HEADS * HD * SEQ]; // V^T [bh][d][key]
__device__ __half g_atth[(size_t)MROWS * DMODEL];   // attention out half [M][1024]

// ===========================================================================
// helpers
// ===========================================================================
__device__ __forceinline__ uint32_t smem_u32(const void* p) {
    uint32_t a;
    asm("{ .reg .u64 t; cvta.to.shared.u64 t, %1; cvt.u32.u64 %0, t; }" : "=r"(a) : "l"(p));
    return a;
}
__device__ __forceinline__ void mma_f16(float c[4], const uint32_t a[4], const uint32_t b[2]) {
    asm volatile(
        "mma.sync.aligned.m16n8k16.row.col.f32.f16.f16.f32 "
        "{%0,%1,%2,%3}, {%4,%5,%6,%7}, {%8,%9}, {%0,%1,%2,%3};"
        : "+f"(c[0]), "+f"(c[1]), "+f"(c[2]), "+f"(c[3])
        : "r"(a[0]), "r"(a[1]), "r"(a[2]), "r"(a[3]), "r"(b[0]), "r"(b[1]));
}
__device__ __forceinline__ void cp_async16(uint32_t saddr, const void* gptr) {
    asm volatile("cp.async.ca.shared.global [%0], [%1], 16;" :: "r"(saddr), "l"(gptr));
}
__device__ __forceinline__ void cp_commit() {
    asm volatile("cp.async.commit_group;" ::: "memory");
}
__device__ __forceinline__ void cp_wait0() {
    asm volatile("cp.async.wait_group 0;" ::: "memory");
}
__device__ __forceinline__ void cp_wait2() {
    asm volatile("cp.async.wait_group 2;" ::: "memory");
}
__device__ __forceinline__ uint32_t pack_h2(float lo, float hi) {
    __half2 h = __floats2half2_rn(lo, hi);
    return *reinterpret_cast<uint32_t*>(&h);
}

// ===========================================================================
// conversion kernels (unchanged from R12)
// ===========================================================================
__global__ __launch_bounds__(256)
void cvt_half_kernel(const float* __restrict__ src, __half* __restrict__ dst, int n2)
{
    int i = blockIdx.x * blockDim.x + threadIdx.x;
    if (i < n2) {
        float2 v = ((const float2*)src)[i];
        ((__half2*)dst)[i] = __floats2half2_rn(v.x, v.y);
    }
}

__global__ __launch_bounds__(256)
void transpose_cvt_kernel(const float* __restrict__ W, __half* __restrict__ Wh, int K, int N)
{
    __shared__ float tile[32][33];
    int bx = blockIdx.x * 32;
    int by = blockIdx.y * 32;
    int tx = threadIdx.x & 31, ty = threadIdx.x >> 5;
#pragma unroll
    for (int i = 0; i < 32; i += 8)
        tile[ty + i][tx] = W[(size_t)(by + ty + i) * N + bx + tx];
    __syncthreads();
#pragma unroll
    for (int i = 0; i < 32; i += 8)
        Wh[(size_t)(bx + ty + i) * K + by + tx] = __float2half_rn(tile[tx][ty + i]);
}

__global__ __launch_bounds__(256)
void vtrans_kernel(const __half* __restrict__ qkvh, __half* __restrict__ vth)
{
    __shared__ __half tile[64 * 72];
    const int kt = blockIdx.x;
    const int bh = blockIdx.y;
    const int b  = bh / HEADS, h = bh % HEADS;
    const int t  = threadIdx.x;

#pragma unroll
    for (int i = 0; i < 2; i++) {
        int idx = t + i * 256;
        int key = idx >> 3, part = idx & 7;
        const uint4* src = (const uint4*)(qkvh + (size_t)(b * SEQ + kt * 64 + key) * QKV_N
                                          + h * (3 * HD) + 2 * HD + part * 8);
        *(uint4*)(tile + key * 72 + part * 8) = *src;
    }
    __syncthreads();

    const int d = t >> 2, ks = (t & 3) * 16;
    __half tmp[16];
#pragma unroll
    for (int k = 0; k < 16; k++) tmp[k] = tile[(ks + k) * 72 + d];
    __half* dst = vth + ((size_t)bh * HD + d) * SEQ + kt * 64 + ks;
    *(uint4*)dst       = *(uint4*)tmp;
    *(uint4*)(dst + 8) = *(uint4*)(tmp + 8);
}

// ===========================================================================
// fp16 mma GEMM + bias (unchanged from R12)
// ===========================================================================
#define GP 40
#define G_ST (128 * GP)
#define G_STAGE (2 * G_ST)
#define GNS 4
#define GEMM_SMEM (GNS * G_STAGE * sizeof(__half))   // 81920

template <bool OUTHALF>
__global__ __launch_bounds__(256, 2)
void gemm_h_kernel(const __half* __restrict__ A, const __half* __restrict__ Bt,
                   const float* __restrict__ bias, void* __restrict__ Cp,
                   int N, int K)
{
    extern __shared__ __half smh[];
    const uint32_t smb = smem_u32(smh);

    const int t    = threadIdx.x;
    const int lane = t & 31;
    const int wid  = t >> 5;
    const int wm   = (wid >> 2) * 64;
    const int wn   = (wid & 3) * 32;
    const int g    = lane >> 2;
    const int t4   = lane & 3;
    const int m0   = blockIdx.y * 128;
    const int n0   = blockIdx.x * 128;

    const int frow = t >> 1;
    const int fseg = (t & 1) * 16;

    float acc[4][4][4];
#pragma unroll
    for (int mi = 0; mi < 4; mi++)
#pragma unroll
        for (int ni = 0; ni < 4; ni++)
#pragma unroll
            for (int r = 0; r < 4; r++) acc[mi][ni][r] = 0.f;

    const int nch = K / 32;

    auto load_chunk = [&](int c, int s) {
        const uint32_t stA = smb + (uint32_t)(s * G_STAGE) * 2u;
        const uint32_t stB = stA + (uint32_t)G_ST * 2u;
        const __half* Ab = A + (size_t)(m0 + frow) * K + c * 32 + fseg;
        cp_async16(stA + (uint32_t)(frow * GP + fseg) * 2u, Ab);
        cp_async16(stA + (uint32_t)(frow * GP + fseg + 8) * 2u, Ab + 8);
        const __half* Bb = Bt + (size_t)(n0 + frow) * K + c * 32 + fseg;
        cp_async16(stB + (uint32_t)(frow * GP + fseg) * 2u, Bb);
        cp_async16(stB + (uint32_t)(frow * GP + fseg + 8) * 2u, Bb + 8);
    };

#pragma unroll
    for (int c = 0; c < GNS - 1; c++) { load_chunk(c, c); cp_commit(); }

    for (int c = 0; c < nch; c++) {
        cp_wait2();
        __syncthreads();

        if (c + GNS - 1 < nch) load_chunk(c + GNS - 1, (c + GNS - 1) & (GNS - 1));
        cp_commit();

        const int s = c & (GNS - 1);
        const __half* as_ = smh + s * G_STAGE;
        const __half* bs_ = as_ + G_ST;

#pragma unroll
        for (int ks = 0; ks < 2; ks++) {
            const int kk = ks * 16;
            uint32_t af[4][4], bf[4][2];
#pragma unroll
            for (int mi = 0; mi < 4; mi++) {
                int r0 = wm + mi * 16 + g;
                af[mi][0] = *(const uint32_t*)(as_ + r0 * GP + kk + 2 * t4);
                af[mi][1] = *(const uint32_t*)(as_ + (r0 + 8) * GP + kk + 2 * t4);
                af[mi][2] = *(const uint32_t*)(as_ + r0 * GP + kk + 2 * t4 + 8);
                af[mi][3] = *(const uint32_t*)(as_ + (r0 + 8) * GP + kk + 2 * t4 + 8);
            }
#pragma unroll
            for (int ni = 0; ni < 4; ni++) {
                int cc = wn + ni * 8 + g;
                bf[ni][0] = *(const uint32_t*)(bs_ + cc * GP + kk + 2 * t4);
                bf[ni][1] = *(const uint32_t*)(bs_ + cc * GP + kk + 2 * t4 + 8);
            }
#pragma unroll
            for (int mi = 0; mi < 4; mi++)
#pragma unroll
                for (int ni = 0; ni < 4; ni++)
                    mma_f16(acc[mi][ni], af[mi], bf[ni]);
        }
    }

#pragma unroll
    for (int mi = 0; mi < 4; mi++) {
        int row = m0 + wm + mi * 16 + g;
#pragma unroll
        for (int ni = 0; ni < 4; ni++) {
            int col = n0 + wn + ni * 8 + 2 * t4;
            float2 bv = *(const float2*)(bias + col);
            if (OUTHALF) {
                __half* C = (__half*)Cp;
                *(uint32_t*)(C + (size_t)row * N + col) =
                    pack_h2(acc[mi][ni][0] + bv.x, acc[mi][ni][1] + bv.y);
                *(uint32_t*)(C + (size_t)(row + 8) * N + col) =
                    pack_h2(acc[mi][ni][2] + bv.x, acc[mi][ni][3] + bv.y);
            } else {
                float* C = (float*)Cp;
                *(float2*)(C + (size_t)row * N + col) =
                    make_float2(acc[mi][ni][0] + bv.x, acc[mi][ni][1] + bv.y);
                *(float2*)(C + (size_t)(row + 8) * N + col) =
                    make_float2(acc[mi][ni][2] + bv.x, acc[mi][ni][3] + bv.y);
            }
        }
    }
}

// ===========================================================================
// fp16 mma flash attention.
// Q fragments in registers (16 regs); K/V cp.async double-buffered.
// Raw fp32 exp summed into l (no half round-trip); P packed to half at PV.
// ===========================================================================
#define AP 72
#define KV_F (64 * AP)                  // halves per K (or V) tile
#define A_STG (2 * KV_F)                // K + V per stage
#define ATT_SMEM (2 * A_STG * sizeof(__half))   // 36864 B

__global__ __launch_bounds__(256, 2)
void attn_h_kernel(const __half* __restrict__ qkvh, const __half* __restrict__ vth,
                   const float* __restrict__ mask, __half* __restrict__ att)
{
    extern __shared__ __half smh[];
    const uint32_t smb = smem_u32(smh);

    const int t    = threadIdx.x;
    const int lane = t & 31;
    const int wid  = t >> 5;
    const int g    = lane >> 2;
    const int t4   = lane & 3;
    const int bh   = blockIdx.y;
    const int b    = bh / HEADS;
    const int h    = bh % HEADS;
    const int q0   = blockIdx.x * 128;

    const int qrow = wid * 16 + g;

    // K/V fill mapping
    const int frow = t >> 2;
    const int fseg = (t & 3) * 16;

    auto load_tile = [&](int kt, int s) {
        const __half* ksrc = qkvh + (size_t)(b * SEQ + kt * 64 + frow) * QKV_N
                           + h * (3 * HD) + HD + fseg;
        const __half* vsrc = vth + ((size_t)bh * HD + frow) * SEQ + kt * 64 + fseg;
        const uint32_t kdst = smb + (uint32_t)(s * A_STG + frow * AP + fseg) * 2u;
        const uint32_t vdst = smb + (uint32_t)(s * A_STG + KV_F + frow * AP + fseg) * 2u;
        cp_async16(kdst, ksrc);
        cp_async16(kdst + 16u, ksrc + 8);
        cp_async16(vdst, vsrc);
        cp_async16(vdst + 16u, vsrc + 8);
    };

    // ---- Q fragments -> registers, x0.125 folded (exact power of 2) ----
    uint32_t qf[4][4];
    {
        const __half* q0p = qkvh + (size_t)(b * SEQ + q0 + qrow) * QKV_N + h * (3 * HD);
        const __half* q1p = q0p + 8 * QKV_N;
        const __half2 sc8 = __floats2half2_rn(0.125f, 0.125f);
#pragma unroll
        for (int j = 0; j < 4; j++) {
            int kk = j * 16;
            __half2 a0 = *(const __half2*)(q0p + kk + 2 * t4);
            __half2 a1 = *(const __half2*)(q1p + kk + 2 * t4);
            __half2 a2 = *(const __half2*)(q0p + kk + 2 * t4 + 8);
            __half2 a3 = *(const __half2*)(q1p + kk + 2 * t4 + 8);
            a0 = __hmul2(a0, sc8); a1 = __hmul2(a1, sc8);
            a2 = __hmul2(a2, sc8); a3 = __hmul2(a3, sc8);
            qf[j][0] = *(uint32_t*)&a0; qf[j][1] = *(uint32_t*)&a1;
            qf[j][2] = *(uint32_t*)&a2; qf[j][3] = *(uint32_t*)&a3;
        }
    }

    float m0 = -1e30f, m1 = -1e30f, l0 = 0.f, l1 = 0.f;
    float acc[8][4];
#pragma unroll
    for (int ni = 0; ni < 8; ni++)
#pragma unroll
        for (int r = 0; r < 4; r++) acc[ni][r] = 0.f;

    load_tile(0, 0);
    cp_commit();

    const int NT = SEQ / 64;
    for (int kt = 0; kt < NT; kt++) {
        const int s = kt & 1;
        cp_wait0();
        __syncthreads();

        if (kt + 1 < NT) { load_tile(kt + 1, s ^ 1); cp_commit(); }

        const __half* Ks = smh + s * A_STG;
        const __half* Vs = Ks + KV_F;

        // ---- scores = Q @ K^T ----
        float sc[8][4];
#pragma unroll
        for (int ni = 0; ni < 8; ni++)
#pragma unroll
            for (int r = 0; r < 4; r++) sc[ni][r] = 0.f;

#pragma unroll
        for (int j = 0; j < 4; j++) {
            const int kk = j * 16;
#pragma unroll
            for (int ni = 0; ni < 8; ni++) {
                uint32_t bf[2];
                bf[0] = *(const uint32_t*)(Ks + (ni * 8 + g) * AP + kk + 2 * t4);
                bf[1] = *(const uint32_t*)(Ks + (ni * 8 + g) * AP + kk + 2 * t4 + 8);
                mma_f16(sc[ni], qf[j], bf);
            }
        }

        // ---- + mask, online softmax (raw fp32 exp; no half round-trip) ----
        {
            const int k0 = kt * 64;
            const float* mr0 = mask + (size_t)(q0 + qrow) * SEQ + k0 + 2 * t4;
            const float* mr1 = mr0 + 8 * SEQ;
            float mx0 = -1e30f, mx1 = -1e30f;
#pragma unroll
            for (int ni = 0; ni < 8; ni++) {
                float2 a = *(const float2*)(mr0 + 8 * ni);
                float2 c = *(const float2*)(mr1 + 8 * ni);
                sc[ni][0] += a.x; sc[ni][1] += a.y;
                sc[ni][2] += c.x; sc[ni][3] += c.y;
                mx0 = fmaxf(mx0, fmaxf(sc[ni][0], sc[ni][1]));
                mx1 = fmaxf(mx1, fmaxf(sc[ni][2], sc[ni][3]));
            }
#pragma unroll
            for (int off = 1; off <= 2; off <<= 1) {
                mx0 = fmaxf(mx0, __shfl_xor_sync(0xffffffffu, mx0, off));
                mx1 = fmaxf(mx1, __shfl_xor_sync(0xffffffffu, mx1, off));
            }
            float mn0 = fmaxf(m0, mx0), mn1 = fmaxf(m1, mx1);
            float c0 = __expf(m0 - mn0), c1 = __expf(m1 - mn1);
            float rs0 = 0.f, rs1 = 0.f;
#pragma unroll
            for (int ni = 0; ni < 8; ni++) {
                sc[ni][0] = __expf(sc[ni][0] - mn0);
                sc[ni][1] = __expf(sc[ni][1] - mn0);
                sc[ni][2] = __expf(sc[ni][2] - mn1);
                sc[ni][3] = __expf(sc[ni][3] - mn1);
                rs0 += sc[ni][0] + sc[ni][1];
                rs1 += sc[ni][2] + sc[ni][3];
            }
#pragma unroll
            for (int off = 1; off <= 2; off <<= 1) {
                rs0 += __shfl_xor_sync(0xffffffffu, rs0, off);
                rs1 += __shfl_xor_sync(0xffffffffu, rs1, off);
            }
            l0 = l0 * c0 + rs0; l1 = l1 * c1 + rs1;
            m0 = mn0; m1 = mn1;
#pragma unroll
            for (int ni = 0; ni < 8; ni++) {
                acc[ni][0] *= c0; acc[ni][1] *= c0;
                acc[ni][2] *= c1; acc[ni][3] *= c1;
            }
        }

        // ---- acc += P @ V : A packed from accumulators, B from V^T ----
#pragma unroll
        for (int j = 0; j < 4; j++) {
            const int kk = j * 16;
            uint32_t af[4];
            af[0] = pack_h2(sc[2 * j][0],     sc[2 * j][1]);
            af[1] = pack_h2(sc[2 * j][2],     sc[2 * j][3]);
            af[2] = pack_h2(sc[2 * j + 1][0], sc[2 * j + 1][1]);
            af[3] = pack_h2(sc[2 * j + 1][2], sc[2 * j + 1][3]);
#pragma unroll
            for (int ni = 0; ni < 8; ni++) {
                uint32_t bf[2];
                bf[0] = *(const uint32_t*)(Vs + (ni * 8 + g) * AP + kk + 2 * t4);
                bf[1] = *(const uint32_t*)(Vs + (ni * 8 + g) * AP + kk + 2 * t4 + 8);
                mma_f16(acc[ni], af, bf);
            }
        }
    }

    // ---- normalize + store half ----
    {
        float inv0 = 1.f / l0, inv1 = 1.f / l1;
        __half* o0 = att + (size_t)(b * SEQ + q0 + qrow) * DMODEL + h * HD + 2 * t4;
        __half* o1 = o0 + 8 * DMODEL;
#pragma unroll
        for (int ni = 0; ni < 8; ni++) {
            *(uint32_t*)(o0 + 8 * ni) = pack_h2(acc[ni][0] * inv0, acc[ni][1] * inv0);
            *(uint32_t*)(o1 + 8 * ni) = pack_h2(acc[ni][2] * inv1, acc[ni][3] * inv1);
        }
    }
}

// ---------------------------------------------------------------------------
extern "C" void kernel_launch(void* const* d_in, const int* in_sizes, int n_in,
                              void* d_out, int out_size)
{
    const float* x     = (const float*)d_in[0];
    const float* mask  = (const float*)d_in[1];
    const float* w_qkv = (const float*)d_in[2];
    const float* b_qkv = (const float*)d_in[3];
    const float* w_out = (const float*)d_in[4];
    const float* b_out = (const float*)d_in[5];
    float* out = (float*)d_out;

    __half *xh, *wqkvh, *wouth, *qkvh, *vthp, *atth;
    cudaGetSymbolAddress((void**)&xh,    g_xh);
    cudaGetSymbolAddress((void**)&wqkvh, g_wqkvh);
    cudaGetSymbolAddress((void**)&wouth, g_wouth);
    cudaGetSymbolAddress((void**)&qkvh,  g_qkvh);
    cudaGetSymbolAddress((void**)&vthp,  g_vth);
    cudaGetSymbolAddress((void**)&atth,  g_atth);

    cudaFuncSetAttribute(gemm_h_kernel<true>, cudaFuncAttributeMaxDynamicSharedMemorySize,
                         (int)GEMM_SMEM);
    cudaFuncSetAttribute(gemm_h_kernel<false>, cudaFuncAttributeMaxDynamicSharedMemorySize,
                         (int)GEMM_SMEM);
    cudaFuncSetAttribute(attn_h_kernel, cudaFuncAttributeMaxDynamicSharedMemorySize,
                         (int)ATT_SMEM);

    // 0) convert operands to half
    cvt_half_kernel<<<(MROWS * DMODEL / 2 + 255) / 256, 256>>>(x, xh, MROWS * DMODEL / 2);
    {
        dim3 g1(QKV_N / 32, DMODEL / 32);
        transpose_cvt_kernel<<<g1, 256>>>(w_qkv, wqkvh, DMODEL, QKV_N);
        dim3 g2(DMODEL / 32, DMODEL / 32);
        transpose_cvt_kernel<<<g2, 256>>>(w_out, wouth, DMODEL, DMODEL);
    }

    // 1) QKV projection (fp16 mma, half output)
    {
        dim3 grid(QKV_N / 128, MROWS / 128);
        gemm_h_kernel<true><<<grid, 256, GEMM_SMEM>>>(xh, wqkvh, b_qkv, qkvh, QKV_N, DMODEL);
    }

    // 1b) transpose V per (b,h)
    {
        dim3 grid(SEQ / 64, BATCH * HEADS);
        vtrans_kernel<<<grid, 256>>>(qkvh, vthp);
    }

    // 2) attention (fp16 mma flash, Q-in-regs, lean softmax)
    {
        dim3 grid(SEQ / 128, BATCH * HEADS);
        attn_h_kernel<<<grid, 256, ATT_SMEM>>>(qkvh, vthp, mask, atth);
    }

    // 3) output projection (fp16 mma, fp32 output)
    {
        dim3 grid(DMODEL / 128, MROWS / 128);
        gemm_h_kernel<false><<<grid, 256, GEMM_SMEM>>>(atth, wouth, b_out, out, DMODEL, DMODEL);
    }
}